// round 11
// baseline (speedup 1.0000x reference)
#include <cuda_runtime.h>
#include <math.h>

#define B_DIM   4096
#define C_DIM   5000
#define G4      1250                 // float4 groups per row
#define HG      625                  // float4 groups per half-row
#define THREADS 640
#define BLOCKS  296                  // 2 blocks per SM, single wave
#define GPT     2
#define MAX_LR  14                   // ceil(4096/296)
#define NWARPS  (THREADS / 32)       // 20
#define NREP    4                    // column-accumulator replicas

#define NSTAGES     4
#define STAGE_BYTES 20000            // HG*16 (logits) + HG*16 (targets)
#define STAGE_T_OFF 10000
#define SMEM_DYN    (NSTAGES * STAGE_BYTES)   // 80 KB

// cross-block column accumulators (zero at load; last block re-zeros each call)
__device__ float g_col_neg[NREP][C_DIM];
__device__ float g_col_pos[NREP][C_DIM];
__device__ float g_blk_rowloss[BLOCKS];
__device__ unsigned int g_done;      // zero-init; last block resets

__device__ __forceinline__ float softplus_f(float z) {
    return (z > 20.f) ? z : log1pf(__expf(z));
}

// targets are {0,1}: tf = exact 0.0f/1.0f via IMAD (no I2F, no predicates)
__device__ __forceinline__ void elem_f(float x, int tt, float& en, float& ep) {
    const float tf = __int_as_float(tt * 0x3f800000);
    const float m  = fmaf(tf, -1.25f, 1.0f);     // 1.0 (neg) or -0.25 (pos)
    const float e  = __expf(x * m);
    ep = e * tf;
    en = e - ep;
}

__device__ __forceinline__ void cp16(void* dst_smem, const void* src) {
    const unsigned d = (unsigned)__cvta_generic_to_shared(dst_smem);
    asm volatile("cp.async.cg.shared.global [%0], [%1], 16;" :: "r"(d), "l"(src));
}
__device__ __forceinline__ void cp_commit() {
    asm volatile("cp.async.commit_group;");
}
template <int N>
__device__ __forceinline__ void cp_wait() {
    asm volatile("cp.async.wait_group %0;" :: "n"(N));
}

__global__ __launch_bounds__(THREADS, 2)
void twl_fused_kernel(const float* __restrict__ logits,
                      const int*   __restrict__ targets,
                      float* __restrict__ out) {
    extern __shared__ char smem_dyn[];
    __shared__ float s_n[MAX_LR * NWARPS];
    __shared__ float s_p[MAX_LR * NWARPS];
    __shared__ float s_loss[MAX_LR];
    __shared__ unsigned int s_ticket;
    __shared__ double s_red[NWARPS];

    const int t    = threadIdx.x;
    const int warp = t >> 5;
    const int lane = t & 31;
    const int bid  = blockIdx.x;

    const bool act = (t < HG);       // threads 625..639 idle in load/math

    const int nrows = (B_DIM - bid + BLOCKS - 1) / BLOCKS;   // 13 or 14
    const int totH  = 2 * nrows;

    float cn[GPT][4], cp[GPT][4];
    #pragma unroll
    for (int j = 0; j < GPT; ++j)
        #pragma unroll
        for (int k = 0; k < 4; ++k) { cn[j][k] = 0.f; cp[j][k] = 0.f; }

    // issue half-row u into ring slot: purely per-thread (thread t copies
    // ONLY the 32B it will itself consume) -> no block barriers anywhere.
    auto issue = [&](int u) {
        char* base = smem_dyn + (u & (NSTAGES - 1)) * STAGE_BYTES;
        if (act) {
            const int row  = bid + (u >> 1) * BLOCKS;
            const int g    = (u & 1) * HG + t;
            const float4* lrow = reinterpret_cast<const float4*>(logits + (size_t)row * C_DIM);
            const int4*   trow = reinterpret_cast<const int4*>(targets + (size_t)row * C_DIM);
            cp16(reinterpret_cast<float4*>(base) + t,                &lrow[g]);
            cp16(reinterpret_cast<int4*>(base + STAGE_T_OFF) + t,   &trow[g]);
        }
        cp_commit();
    };

    // prologue: lookahead 3 half-rows
    issue(0); issue(1); issue(2);

    float rn = 0.f, rp = 0.f;
    for (int u = 0; u < totH; ++u) {
        const int rem = totH - 1 - u;       // groups younger than u after issue
        if (rem >= 3) { issue(u + 3); cp_wait<3>(); }
        else if (rem == 2) cp_wait<2>();
        else if (rem == 1) cp_wait<1>();
        else               cp_wait<0>();

        const char* base = smem_dyn + (u & (NSTAGES - 1)) * STAGE_BYTES;
        if (act) {
            const float4 x  = reinterpret_cast<const float4*>(base)[t];
            const int4   tg = reinterpret_cast<const int4*>(base + STAGE_T_OFF)[t];
            const int j = u & 1;
            float en, ep;
            elem_f(x.x, tg.x, en, ep); rn += en; rp += ep; cn[j][0] += en; cp[j][0] += ep;
            elem_f(x.y, tg.y, en, ep); rn += en; rp += ep; cn[j][1] += en; cp[j][1] += ep;
            elem_f(x.z, tg.z, en, ep); rn += en; rp += ep; cn[j][2] += en; cp[j][2] += ep;
            elem_f(x.w, tg.w, en, ep); rn += en; rp += ep; cn[j][3] += en; cp[j][3] += ep;
        }

        if (u & 1) {   // row complete: warp-local reduce, no cross-warp sync
            #pragma unroll
            for (int o = 16; o > 0; o >>= 1) {
                rn += __shfl_down_sync(0xffffffffu, rn, o);
                rp += __shfl_down_sync(0xffffffffu, rp, o);
            }
            if (lane == 0) {
                s_n[(u >> 1) * NWARPS + warp] = rn;
                s_p[(u >> 1) * NWARPS + warp] = rp;
            }
            rn = 0.f; rp = 0.f;
        }
    }

    // flush column partials via L2 REDs into this block's replica
    {
        float* __restrict__ rep_n = g_col_neg[bid & (NREP - 1)];
        float* __restrict__ rep_p = g_col_pos[bid & (NREP - 1)];
        if (act) {
            #pragma unroll
            for (int j = 0; j < GPT; ++j) {
                const int g = j * HG + t;
                #pragma unroll
                for (int k = 0; k < 4; ++k) {
                    atomicAdd(&rep_n[4 * g + k], cn[j][k]);
                    atomicAdd(&rep_p[4 * g + k], cp[j][k]);
                }
            }
        }
    }

    __syncthreads();   // s_n/s_p complete across warps

    if (warp < nrows) {
        float vn = (lane < NWARPS) ? s_n[warp * NWARPS + lane] : 0.f;
        float vp = (lane < NWARPS) ? s_p[warp * NWARPS + lane] : 0.f;
        #pragma unroll
        for (int o = 16; o > 0; o >>= 1) {
            vn += __shfl_down_sync(0xffffffffu, vn, o);
            vp += __shfl_down_sync(0xffffffffu, vp, o);
        }
        if (lane == 0) {
            float loss = 0.f;
            if (vn > 0.f && vp > 0.f) {
                const float z = __logf(vn) + 4.f * __logf(vp);
                loss = softplus_f(z);
            }
            s_loss[warp] = loss;
        }
    }
    __syncthreads();
    if (warp == 0) {
        float v = (lane < nrows) ? s_loss[lane] : 0.f;
        #pragma unroll
        for (int o = 16; o > 0; o >>= 1)
            v += __shfl_down_sync(0xffffffffu, v, o);
        if (lane == 0) g_blk_rowloss[bid] = v;
    }

    __threadfence();
    __syncthreads();
    if (t == 0) s_ticket = atomicAdd(&g_done, 1u);
    __syncthreads();
    if (s_ticket != BLOCKS - 1) return;

    // ---- last block: finalize ----
    __threadfence();

    double loc = 0.0;
    for (int c = t; c < C_DIM; c += THREADS) {
        float sn = 0.f, sp = 0.f;
        #pragma unroll
        for (int r = 0; r < NREP; ++r) {
            sn += g_col_neg[r][c];
            sp += g_col_pos[r][c];
            g_col_neg[r][c] = 0.f;
            g_col_pos[r][c] = 0.f;
        }
        if (sn > 0.f && sp > 0.f) {
            const float z = __logf(sn) + 4.f * __logf(sp);
            loc += (double)softplus_f(z);
        }
    }
    double rs = 0.0;
    for (int b = t; b < BLOCKS; b += THREADS)
        rs += (double)g_blk_rowloss[b];

    #pragma unroll
    for (int o = 16; o > 0; o >>= 1) {
        loc += __shfl_down_sync(0xffffffffu, loc, o);
        rs  += __shfl_down_sync(0xffffffffu, rs, o);
    }
    if (lane == 0) s_red[warp] = loc;
    __syncthreads();
    double loc_tot = 0.0;
    if (warp == 0 && lane == 0) {
        #pragma unroll
        for (int w = 0; w < NWARPS; ++w) loc_tot += s_red[w];
    }
    __syncthreads();
    if (lane == 0) s_red[warp] = rs;
    __syncthreads();
    if (warp == 0 && lane == 0) {
        double r = 0.0;
        #pragma unroll
        for (int w = 0; w < NWARPS; ++w) r += s_red[w];
        out[0] = (float)(0.5 * (r / (double)B_DIM + loc_tot / (double)C_DIM));
        g_done = 0u;
    }
}

extern "C" void kernel_launch(void* const* d_in, const int* in_sizes, int n_in,
                              void* d_out, int out_size) {
    const float* logits  = (const float*)d_in[0];
    const int*   targets = (const int*)d_in[1];
    float* out = (float*)d_out;

    cudaFuncSetAttribute(twl_fused_kernel,
                         cudaFuncAttributeMaxDynamicSharedMemorySize, SMEM_DYN);
    twl_fused_kernel<<<BLOCKS, THREADS, SMEM_DYN>>>(logits, targets, out);
}

// round 12
// speedup vs baseline: 1.3704x; 1.3704x over previous
#include <cuda_runtime.h>
#include <math.h>

#define B_DIM   4096
#define C_DIM   5000
#define G4      1250                 // float4 groups per row
#define THREADS 640
#define BLOCKS  296                  // 2 blocks per SM, single wave
#define GPT     2
#define MAX_LR  14                   // ceil(4096/296)
#define NWARPS  (THREADS / 32)       // 20
#define NREP    4                    // column-accumulator replicas

#define SMEM_DYN (MAX_LR * THREADS * (int)sizeof(float2))   // 71680 B

// cross-block column accumulators (zero at load; last block re-zeros each call)
__device__ float g_col_neg[NREP][C_DIM];
__device__ float g_col_pos[NREP][C_DIM];
__device__ float g_blk_rowloss[BLOCKS];
__device__ unsigned int g_done;      // zero-init; last block resets

__device__ __forceinline__ float softplus_f(float z) {
    return (z > 20.f) ? z : log1pf(__expf(z));
}

// targets are {0,1}: tf exact 0.0f/1.0f via IMAD; all accums FMA-folded
__device__ __forceinline__ void elem_f(float x, int tt,
                                       float& rn, float& rp,
                                       float& cnk, float& cpk) {
    const float tf = __int_as_float(tt * 0x3f800000);
    const float uf = 1.0f - tf;
    const float m  = fmaf(tf, -1.25f, 1.0f);     // 1.0 (neg) or -0.25 (pos)
    const float e  = __expf(x * m);
    rp  = fmaf(e, tf, rp);
    cpk = fmaf(e, tf, cpk);
    rn  = fmaf(e, uf, rn);
    cnk = fmaf(e, uf, cnk);
}

__global__ __launch_bounds__(THREADS, 2)
void twl_fused_kernel(const float* __restrict__ logits,
                      const int*   __restrict__ targets,
                      float* __restrict__ out) {
    extern __shared__ float2 s_part[];           // [MAX_LR][THREADS]
    __shared__ float s_loss[MAX_LR];
    __shared__ unsigned int s_ticket;
    __shared__ double s_red[NWARPS];

    const int t    = threadIdx.x;
    const int warp = t >> 5;
    const int lane = t & 31;
    const int bid  = blockIdx.x;

    const int  g0   = t;                  // always < 1250
    const int  g1   = t + THREADS;
    const bool has1 = (g1 < G4);

    float cn[GPT][4], cp[GPT][4];
    #pragma unroll
    for (int j = 0; j < GPT; ++j)
        #pragma unroll
        for (int k = 0; k < 4; ++k) { cn[j][k] = 0.f; cp[j][k] = 0.f; }

    // prologue: load group 0 of first row
    int row = bid;
    float4 x0; int4 t0;
    {
        const float4* lr0 = reinterpret_cast<const float4*>(logits + (size_t)row * C_DIM);
        const int4*   tr0 = reinterpret_cast<const int4*>(targets + (size_t)row * C_DIM);
        x0 = lr0[g0];
        t0 = tr0[g0];
    }

    int lr = 0;
    for (; row < B_DIM; row += BLOCKS, ++lr) {
        const float4* __restrict__ lrow =
            reinterpret_cast<const float4*>(logits + (size_t)row * C_DIM);
        const int4* __restrict__ trow =
            reinterpret_cast<const int4*>(targets + (size_t)row * C_DIM);

        // current row's group-1 load
        float4 x1; int4 t1;
        if (has1) { x1 = lrow[g1]; t1 = trow[g1]; }

        // prefetch next row's group-0 load
        const int nrow = row + BLOCKS;
        float4 px; int4 pt;
        if (nrow < B_DIM) {
            const float4* nl = reinterpret_cast<const float4*>(logits + (size_t)nrow * C_DIM);
            const int4*   nt = reinterpret_cast<const int4*>(targets + (size_t)nrow * C_DIM);
            px = nl[g0];
            pt = nt[g0];
        }

        float rn = 0.f, rp = 0.f;

        elem_f(x0.x, t0.x, rn, rp, cn[0][0], cp[0][0]);
        elem_f(x0.y, t0.y, rn, rp, cn[0][1], cp[0][1]);
        elem_f(x0.z, t0.z, rn, rp, cn[0][2], cp[0][2]);
        elem_f(x0.w, t0.w, rn, rp, cn[0][3], cp[0][3]);
        if (has1) {
            elem_f(x1.x, t1.x, rn, rp, cn[1][0], cp[1][0]);
            elem_f(x1.y, t1.y, rn, rp, cn[1][1], cp[1][1]);
            elem_f(x1.z, t1.z, rn, rp, cn[1][2], cp[1][2]);
            elem_f(x1.w, t1.w, rn, rp, cn[1][3], cp[1][3]);
        }

        // ONE store instead of 10 SHFL + 10 FADD: no serial chain, no barrier
        s_part[lr * THREADS + t] = make_float2(rn, rp);

        x0 = px; t0 = pt;   // rotate prefetch
    }

    const int nrows = lr;

    // flush column partials via L2 REDs into this block's replica
    {
        float* __restrict__ rep_n = g_col_neg[bid & (NREP - 1)];
        float* __restrict__ rep_p = g_col_pos[bid & (NREP - 1)];
        #pragma unroll
        for (int j = 0; j < GPT; ++j) {
            const int g = t + j * THREADS;
            if (g < G4) {
                #pragma unroll
                for (int k = 0; k < 4; ++k) {
                    atomicAdd(&rep_n[4 * g + k], cn[j][k]);
                    atomicAdd(&rep_p[4 * g + k], cp[j][k]);
                }
            }
        }
    }

    __syncthreads();   // s_part complete

    // warp w reduces row w: 640 float2 partials -> row loss
    if (warp < nrows) {
        float vn = 0.f, vp = 0.f;
        #pragma unroll
        for (int k = 0; k < THREADS / 32; ++k) {
            const float2 v = s_part[warp * THREADS + lane + 32 * k];
            vn += v.x; vp += v.y;
        }
        #pragma unroll
        for (int o = 16; o > 0; o >>= 1) {
            vn += __shfl_down_sync(0xffffffffu, vn, o);
            vp += __shfl_down_sync(0xffffffffu, vp, o);
        }
        if (lane == 0) {
            float loss = 0.f;
            if (vn > 0.f && vp > 0.f) {
                const float z = __logf(vn) + 4.f * __logf(vp);
                loss = softplus_f(z);
            }
            s_loss[warp] = loss;
        }
    }
    __syncthreads();
    if (warp == 0) {
        float v = (lane < nrows) ? s_loss[lane] : 0.f;
        #pragma unroll
        for (int o = 16; o > 0; o >>= 1)
            v += __shfl_down_sync(0xffffffffu, v, o);
        if (lane == 0) g_blk_rowloss[bid] = v;
    }

    __threadfence();
    __syncthreads();
    if (t == 0) s_ticket = atomicAdd(&g_done, 1u);
    __syncthreads();
    if (s_ticket != BLOCKS - 1) return;

    // ---- last block: finalize ----
    __threadfence();

    double loc = 0.0;
    for (int c = t; c < C_DIM; c += THREADS) {
        float sn = 0.f, sp = 0.f;
        #pragma unroll
        for (int r = 0; r < NREP; ++r) {
            sn += g_col_neg[r][c];
            sp += g_col_pos[r][c];
            g_col_neg[r][c] = 0.f;
            g_col_pos[r][c] = 0.f;
        }
        if (sn > 0.f && sp > 0.f) {
            const float z = __logf(sn) + 4.f * __logf(sp);
            loc += (double)softplus_f(z);
        }
    }
    double rs = 0.0;
    for (int b = t; b < BLOCKS; b += THREADS)
        rs += (double)g_blk_rowloss[b];

    #pragma unroll
    for (int o = 16; o > 0; o >>= 1) {
        loc += __shfl_down_sync(0xffffffffu, loc, o);
        rs  += __shfl_down_sync(0xffffffffu, rs, o);
    }
    if (lane == 0) s_red[warp] = loc;
    __syncthreads();
    double loc_tot = 0.0;
    if (warp == 0 && lane == 0) {
        #pragma unroll
        for (int w = 0; w < NWARPS; ++w) loc_tot += s_red[w];
    }
    __syncthreads();
    if (lane == 0) s_red[warp] = rs;
    __syncthreads();
    if (warp == 0 && lane == 0) {
        double r = 0.0;
        #pragma unroll
        for (int w = 0; w < NWARPS; ++w) r += s_red[w];
        out[0] = (float)(0.5 * (r / (double)B_DIM + loc_tot / (double)C_DIM));
        g_done = 0u;
    }
}

extern "C" void kernel_launch(void* const* d_in, const int* in_sizes, int n_in,
                              void* d_out, int out_size) {
    const float* logits  = (const float*)d_in[0];
    const int*   targets = (const int*)d_in[1];
    float* out = (float*)d_out;

    cudaFuncSetAttribute(twl_fused_kernel,
                         cudaFuncAttributeMaxDynamicSharedMemorySize, SMEM_DYN);
    twl_fused_kernel<<<BLOCKS, THREADS, SMEM_DYN>>>(logits, targets, out);
}

// round 13
// speedup vs baseline: 1.8990x; 1.3857x over previous
#include <cuda_runtime.h>
#include <math.h>

#define B_DIM   4096
#define C_DIM   5000
#define G4      1250                 // float4 groups per row
#define THREADS 640
#define BLOCKS  296                  // 2 blocks per SM, single wave
#define GPT     2
#define MAX_LR  14                   // ceil(4096/296)
#define NWARPS  (THREADS / 32)       // 20
#define NREP    4                    // column-accumulator replicas

#define SMEM_DYN (MAX_LR * THREADS * (int)sizeof(float2))   // 71680 B

// cross-block column accumulators as float4 (16B-aligned for red.v4)
__device__ __align__(16) float4 g_col_neg[NREP][G4];
__device__ __align__(16) float4 g_col_pos[NREP][G4];
__device__ float g_blk_rowloss[BLOCKS];
__device__ unsigned int g_done;      // zero-init; last block resets

__device__ __forceinline__ float softplus_f(float z) {
    return (z > 20.f) ? z : log1pf(__expf(z));
}

// vectorized global float reduction (sm_90+): one op, 16 bytes
__device__ __forceinline__ void red_v4(float4* addr, const float* v) {
    asm volatile("red.global.add.v4.f32 [%0], {%1, %2, %3, %4};"
                 :: "l"(addr), "f"(v[0]), "f"(v[1]), "f"(v[2]), "f"(v[3])
                 : "memory");
}

// targets are {0,1}: tf exact 0.0f/1.0f via IMAD; all accums FMA-folded
__device__ __forceinline__ void elem_f(float x, int tt,
                                       float& rn, float& rp,
                                       float& cnk, float& cpk) {
    const float tf = __int_as_float(tt * 0x3f800000);
    const float uf = 1.0f - tf;
    const float m  = fmaf(tf, -1.25f, 1.0f);     // 1.0 (neg) or -0.25 (pos)
    const float e  = __expf(x * m);
    rp  = fmaf(e, tf, rp);
    cpk = fmaf(e, tf, cpk);
    rn  = fmaf(e, uf, rn);
    cnk = fmaf(e, uf, cnk);
}

__global__ __launch_bounds__(THREADS, 2)
void twl_fused_kernel(const float* __restrict__ logits,
                      const int*   __restrict__ targets,
                      float* __restrict__ out) {
    extern __shared__ float2 s_part[];           // [MAX_LR][THREADS]
    __shared__ float s_loss[MAX_LR];
    __shared__ unsigned int s_ticket;
    __shared__ double s_red[NWARPS];

    const int t    = threadIdx.x;
    const int warp = t >> 5;
    const int lane = t & 31;
    const int bid  = blockIdx.x;

    const int  g0   = t;                  // always < 1250
    const int  g1   = t + THREADS;
    const bool has1 = (g1 < G4);

    const int nrows = (B_DIM - bid + BLOCKS - 1) / BLOCKS;   // 13 or 14

    float cn[GPT][4], cp[GPT][4];
    #pragma unroll
    for (int j = 0; j < GPT; ++j)
        #pragma unroll
        for (int k = 0; k < 4; ++k) { cn[j][k] = 0.f; cp[j][k] = 0.f; }

    // flush current accumulators into this block's replica, then zero them
    auto flush_cols = [&]() {
        float4* __restrict__ rep_n = g_col_neg[bid & (NREP - 1)];
        float4* __restrict__ rep_p = g_col_pos[bid & (NREP - 1)];
        #pragma unroll
        for (int j = 0; j < GPT; ++j) {
            const int g = t + j * THREADS;
            if (g < G4) {
                red_v4(&rep_n[g], cn[j]);
                red_v4(&rep_p[g], cp[j]);
                #pragma unroll
                for (int k = 0; k < 4; ++k) { cn[j][k] = 0.f; cp[j][k] = 0.f; }
            }
        }
    };

    // prologue: load group 0 of first row
    int row = bid;
    float4 x0; int4 t0;
    {
        const float4* lr0 = reinterpret_cast<const float4*>(logits + (size_t)row * C_DIM);
        const int4*   tr0 = reinterpret_cast<const int4*>(targets + (size_t)row * C_DIM);
        x0 = lr0[g0];
        t0 = tr0[g0];
    }

    int lr = 0;
    for (; row < B_DIM; row += BLOCKS, ++lr) {
        const float4* __restrict__ lrow =
            reinterpret_cast<const float4*>(logits + (size_t)row * C_DIM);
        const int4* __restrict__ trow =
            reinterpret_cast<const int4*>(targets + (size_t)row * C_DIM);

        // current row's group-1 load
        float4 x1; int4 t1;
        if (has1) { x1 = lrow[g1]; t1 = trow[g1]; }

        // prefetch next row's group-0 load
        const int nrow = row + BLOCKS;
        float4 px; int4 pt;
        if (nrow < B_DIM) {
            const float4* nl = reinterpret_cast<const float4*>(logits + (size_t)nrow * C_DIM);
            const int4*   nt = reinterpret_cast<const int4*>(targets + (size_t)nrow * C_DIM);
            px = nl[g0];
            pt = nt[g0];
        }

        float rn = 0.f, rp = 0.f;

        elem_f(x0.x, t0.x, rn, rp, cn[0][0], cp[0][0]);
        elem_f(x0.y, t0.y, rn, rp, cn[0][1], cp[0][1]);
        elem_f(x0.z, t0.z, rn, rp, cn[0][2], cp[0][2]);
        elem_f(x0.w, t0.w, rn, rp, cn[0][3], cp[0][3]);
        if (has1) {
            elem_f(x1.x, t1.x, rn, rp, cn[1][0], cp[1][0]);
            elem_f(x1.y, t1.y, rn, rp, cn[1][1], cp[1][1]);
            elem_f(x1.z, t1.z, rn, rp, cn[1][2], cp[1][2]);
            elem_f(x1.w, t1.w, rn, rp, cn[1][3], cp[1][3]);
        }

        // ONE store instead of a serial shuffle chain
        s_part[lr * THREADS + t] = make_float2(rn, rp);

        // mid-loop flush: these REDs hide under the last ~4 rows of streaming
        if (lr == nrows - 4) flush_cols();

        x0 = px; t0 = pt;   // rotate prefetch
    }

    // final (partial) flush — only rows since the mid-flush, exposed tail is small
    flush_cols();

    __syncthreads();   // s_part complete

    // warp w reduces row w: 640 float2 partials -> row loss
    if (warp < nrows) {
        float vn = 0.f, vp = 0.f;
        #pragma unroll
        for (int k = 0; k < THREADS / 32; ++k) {
            const float2 v = s_part[warp * THREADS + lane + 32 * k];
            vn += v.x; vp += v.y;
        }
        #pragma unroll
        for (int o = 16; o > 0; o >>= 1) {
            vn += __shfl_down_sync(0xffffffffu, vn, o);
            vp += __shfl_down_sync(0xffffffffu, vp, o);
        }
        if (lane == 0) {
            float loss = 0.f;
            if (vn > 0.f && vp > 0.f) {
                const float z = __logf(vn) + 4.f * __logf(vp);
                loss = softplus_f(z);
            }
            s_loss[warp] = loss;
        }
    }
    __syncthreads();
    if (warp == 0) {
        float v = (lane < nrows) ? s_loss[lane] : 0.f;
        #pragma unroll
        for (int o = 16; o > 0; o >>= 1)
            v += __shfl_down_sync(0xffffffffu, v, o);
        if (lane == 0) g_blk_rowloss[bid] = v;
    }

    __threadfence();
    __syncthreads();
    if (t == 0) s_ticket = atomicAdd(&g_done, 1u);
    __syncthreads();
    if (s_ticket != BLOCKS - 1) return;

    // ---- last block: finalize ----
    __threadfence();

    double loc = 0.0;
    for (int g = t; g < G4; g += THREADS) {
        float4 sn = make_float4(0.f, 0.f, 0.f, 0.f);
        float4 sp = make_float4(0.f, 0.f, 0.f, 0.f);
        #pragma unroll
        for (int r = 0; r < NREP; ++r) {
            const float4 vn = g_col_neg[r][g];
            const float4 vp = g_col_pos[r][g];
            sn.x += vn.x; sn.y += vn.y; sn.z += vn.z; sn.w += vn.w;
            sp.x += vp.x; sp.y += vp.y; sp.z += vp.z; sp.w += vp.w;
            g_col_neg[r][g] = make_float4(0.f, 0.f, 0.f, 0.f);
            g_col_pos[r][g] = make_float4(0.f, 0.f, 0.f, 0.f);
        }
        const float n4[4] = {sn.x, sn.y, sn.z, sn.w};
        const float p4[4] = {sp.x, sp.y, sp.z, sp.w};
        #pragma unroll
        for (int k = 0; k < 4; ++k) {
            if (n4[k] > 0.f && p4[k] > 0.f) {
                const float z = __logf(n4[k]) + 4.f * __logf(p4[k]);
                loc += (double)softplus_f(z);
            }
        }
    }
    double rs = 0.0;
    for (int b = t; b < BLOCKS; b += THREADS)
        rs += (double)g_blk_rowloss[b];

    #pragma unroll
    for (int o = 16; o > 0; o >>= 1) {
        loc += __shfl_down_sync(0xffffffffu, loc, o);
        rs  += __shfl_down_sync(0xffffffffu, rs, o);
    }
    if (lane == 0) s_red[warp] = loc;
    __syncthreads();
    double loc_tot = 0.0;
    if (warp == 0 && lane == 0) {
        #pragma unroll
        for (int w = 0; w < NWARPS; ++w) loc_tot += s_red[w];
    }
    __syncthreads();
    if (lane == 0) s_red[warp] = rs;
    __syncthreads();
    if (warp == 0 && lane == 0) {
        double r = 0.0;
        #pragma unroll
        for (int w = 0; w < NWARPS; ++w) r += s_red[w];
        out[0] = (float)(0.5 * (r / (double)B_DIM + loc_tot / (double)C_DIM));
        g_done = 0u;
    }
}

extern "C" void kernel_launch(void* const* d_in, const int* in_sizes, int n_in,
                              void* d_out, int out_size) {
    const float* logits  = (const float*)d_in[0];
    const int*   targets = (const int*)d_in[1];
    float* out = (float*)d_out;

    cudaFuncSetAttribute(twl_fused_kernel,
                         cudaFuncAttributeMaxDynamicSharedMemorySize, SMEM_DYN);
    twl_fused_kernel<<<BLOCKS, THREADS, SMEM_DYN>>>(logits, targets, out);
}